// round 9
// baseline (speedup 1.0000x reference)
#include <cuda_runtime.h>
#include <cuda_bf16.h>
#include <cstdint>

#define WTE (15 * 64 * 4096)

__device__ __align__(16) __nv_bfloat16 g_Whi[WTE];
__device__ __align__(16) __nv_bfloat16 g_Wlo[WTE];

// group of each path: 0 -> Lout0, 1 -> Lout1, 2 -> Lout2
__constant__ int c_grp[15] = {0,1,2,1,2,0,1,1,2,2,1,2,2,0,1};

// W scratch: tiles [p][a][c][b] bf16 hi/lo, from w[p][c][a][b]
__global__ void prep_w(const float* __restrict__ w) {
    int d = blockIdx.x * 256 + threadIdx.x;
    if (d >= WTE) return;
    int p = d >> 18, a = (d >> 12) & 63, c = (d >> 6) & 63, b = d & 63;
    float f = w[(p << 18) | (c << 12) | (a << 6) | b];
    __nv_bfloat16 hi = __float2bfloat16(f);
    g_Whi[d] = hi;
    g_Wlo[d] = __float2bfloat16(f - __bfloat162float(hi));
}

// ---------- smem byte layout ----------
#define P_OFF    93696
#define P_STRIDE 36864
#define W_OFF    167424
#define W_STRIDE 18432
#define SMEM_TOT 222720

__device__ __forceinline__ uint32_t smem_u32(const void* p) {
    uint32_t a;
    asm("{ .reg .u64 t; cvta.to.shared.u64 t, %1; cvt.u32.u64 %0, t; }" : "=r"(a) : "l"(p));
    return a;
}
__device__ __forceinline__ uint32_t pk2(__nv_bfloat16 a, __nv_bfloat16 b) {
    __nv_bfloat162 t(a, b);
    return *(uint32_t*)&t;
}
__device__ __forceinline__ uint32_t cvt2(float lo, float hi) {
    uint32_t r;
    asm("cvt.rn.bf16x2.f32 %0, %1, %2;" : "=r"(r) : "f"(hi), "f"(lo));
    return r;
}

#define LDSM4(r, addr) asm volatile( \
    "ldmatrix.sync.aligned.m8n8.x4.shared.b16 {%0,%1,%2,%3}, [%4];" \
    : "=r"((r)[0]), "=r"((r)[1]), "=r"((r)[2]), "=r"((r)[3]) : "r"(addr))

#define MMAB(d, a, bb0, bb1) asm volatile( \
    "mma.sync.aligned.m16n8k16.row.col.f32.bf16.bf16.f32 " \
    "{%0,%1,%2,%3}, {%4,%5,%6,%7}, {%8,%9}, {%0,%1,%2,%3};" \
    : "+f"((d)[0]), "+f"((d)[1]), "+f"((d)[2]), "+f"((d)[3]) \
    : "r"((a)[0]), "r"((a)[1]), "r"((a)[2]), "r"((a)[3]), "r"(bb0), "r"(bb1))

// Consumer MMA: MF m-frags x full n=64 (8 n-frags), 3 bf16 passes.
template<int MF>
__device__ __forceinline__ void warp_mma(float acc[][8][4], int m0,
                                         uint32_t pPhi, uint32_t pPlo,
                                         uint32_t pWh, uint32_t pWl, int lane) {
    const uint32_t aoff = (uint32_t)((lane & 15) * 144 + ((lane >> 4) << 4));
    const uint32_t boff = (uint32_t)(((lane & 7) + ((lane >> 4) & 1) * 8) * 144 + (lane & 8) * 2);
#pragma unroll
    for (int ks = 0; ks < 4; ks++) {
        const uint32_t kb = ks * 32;
        uint32_t ah[MF][4], al[MF][4];
#pragma unroll
        for (int mi = 0; mi < MF; mi++) {
            uint32_t o = (uint32_t)((m0 + mi * 16) * 144) + kb + aoff;
            LDSM4(ah[mi], pPhi + o);
            LDSM4(al[mi], pPlo + o);
        }
        uint32_t bh[4][4], bl[4][4];
#pragma unroll
        for (int nj = 0; nj < 4; nj++) {
            uint32_t o = (uint32_t)((nj * 16) * 144) + kb + boff;
            LDSM4(bh[nj], pWh + o);
            LDSM4(bl[nj], pWl + o);
        }
#pragma unroll
        for (int mi = 0; mi < MF; mi++)
#pragma unroll
            for (int ni = 0; ni < 8; ni++) {
                int nj = ni >> 1, s = (ni & 1) * 2;
                MMAB(acc[mi][ni], ah[mi], bh[nj][s], bh[nj][s + 1]);
                MMAB(acc[mi][ni], al[mi], bh[nj][s], bh[nj][s + 1]);
                MMAB(acc[mi][ni], ah[mi], bl[nj][s], bl[nj][s + 1]);
            }
    }
}

// 128 producer threads issue the whole 18KB W tile (hi+lo) via cp.async
__device__ __forceinline__ void prefetch_w(int p, int a, int slot, uint32_t sb, int ptid) {
    const size_t tile = ((size_t)(p * 64 + a)) << 12;
#pragma unroll
    for (int q = 0; q < 8; q++) {
        int i = ptid + 128 * q;
        int half = i >> 9, r = i & 511;
        int cR = r >> 3, seg = r & 7;
        const __nv_bfloat16* src = (half ? g_Wlo : g_Whi) + tile + cR * 64 + seg * 8;
        uint32_t dst = sb + W_OFF + slot * W_STRIDE + (half * 64 + cR) * 144 + seg * 16;
        asm volatile("cp.async.cg.shared.global [%0], [%1], 16;" :: "r"(dst), "l"(src));
    }
}

#define G8(nm, off) float nm[8]; { const float4* q_ = (const float4*)(bz + (off) + b0); \
    float4 t0_ = q_[0], t1_ = q_[1]; nm[0]=t0_.x; nm[1]=t0_.y; nm[2]=t0_.z; nm[3]=t0_.w; \
    nm[4]=t1_.x; nm[5]=t1_.y; nm[6]=t1_.z; nm[7]=t1_.w; }

__device__ __forceinline__ void gen_chunk(int p, int g, int a, int nzv,
                                          const float* smemf, char* smemc,
                                          uint32_t phi_off, int ptid) {
    const int tasks = (g == 2) ? 1024 : (g == 1 ? 384 : 128);
    for (int t = ptid; t < tasks; t += 128) {
        const int row = t >> 3;
        const int b0 = (t & 7) << 3;
        int z, u;
        if (g == 2)      { z = row / 9; u = row - z * 9; }
        else if (g == 1) { z = row / 3; u = row - z * 3; }
        else             { z = row;     u = 0; }
        if (z > nzv - 1) z = nzv - 1;
        const float* ax = smemf + z * 833;
        const float* bz = smemf + 11664 + z * 840;
        float v[8];
        switch (p) {
        case 0: { G8(s, 0); float A = ax[a];
#pragma unroll
            for (int j = 0; j < 8; j++) v[j] = A * s[j]; } break;
        case 1: { G8(s, 64 + u * 64); float A = ax[a];
#pragma unroll
            for (int j = 0; j < 8; j++) v[j] = A * s[j]; } break;
        case 2: { G8(s, 256 + u * 64); float A = ax[a];
#pragma unroll
            for (int j = 0; j < 8; j++) v[j] = A * s[j]; } break;
        case 3: { G8(s, 0); float A = ax[64 + 3 * a + u];
#pragma unroll
            for (int j = 0; j < 8; j++) v[j] = A * s[j]; } break;
        case 4: { G8(s, 64 + (u % 3) * 64); float A = ax[64 + 3 * a + u / 3];
#pragma unroll
            for (int j = 0; j < 8; j++) v[j] = A * s[j]; } break;
        case 5: { G8(q0, 64); G8(q1, 128); G8(q2, 192);
            const float* av = ax + 64 + 3 * a;
#pragma unroll
            for (int j = 0; j < 8; j++)
                v[j] = fmaf(av[2], q2[j], fmaf(av[1], q1[j], av[0] * q0[j])); } break;
        case 6: { int u1 = (u + 1) % 3, u2 = (u + 2) % 3;
            G8(qa, 64 + u2 * 64); G8(qb, 64 + u1 * 64);
            const float* av = ax + 64 + 3 * a;
#pragma unroll
            for (int j = 0; j < 8; j++) v[j] = av[u1] * qa[j] - av[u2] * qb[j]; } break;
        case 7: { G8(q0, 256 + (3 * u) * 64); G8(q1, 256 + (3 * u + 1) * 64); G8(q2, 256 + (3 * u + 2) * 64);
            const float* av = ax + 64 + 3 * a;
#pragma unroll
            for (int j = 0; j < 8; j++)
                v[j] = fmaf(av[2], q2[j], fmaf(av[1], q1[j], av[0] * q0[j])); } break;
        case 8: { int e = u / 3, gg = u % 3, g1 = (gg + 1) % 3, g2 = (gg + 2) % 3;
            G8(qa, 256 + (3 * e + g2) * 64); G8(qb, 256 + (3 * e + g1) * 64);
            const float* av = ax + 64 + 3 * a;
#pragma unroll
            for (int j = 0; j < 8; j++) v[j] = av[g1] * qa[j] - av[g2] * qb[j]; } break;
        case 9: { G8(s, 0); float A = ax[256 + 9 * a + u];
#pragma unroll
            for (int j = 0; j < 8; j++) v[j] = A * s[j]; } break;
        case 10: { G8(q0, 64); G8(q1, 128); G8(q2, 192);
            const float* m = ax + 256 + 9 * a + 3 * u;
#pragma unroll
            for (int j = 0; j < 8; j++)
                v[j] = fmaf(m[2], q2[j], fmaf(m[1], q1[j], m[0] * q0[j])); } break;
        case 11: { int d = u / 3, gg = u % 3, g1 = (gg + 1) % 3, g2 = (gg + 2) % 3;
            G8(qa, 64 + g2 * 64); G8(qb, 64 + g1 * 64);
            const float* m = ax + 256 + 9 * a + 3 * d;
#pragma unroll
            for (int j = 0; j < 8; j++) v[j] = m[g1] * qa[j] - m[g2] * qb[j]; } break;
        case 12: { int d = u / 3, f = u % 3;
            const float* m = ax + 256 + 9 * a + 3 * d;
            G8(q0, 256 + (3 * f) * 64); G8(q1, 256 + (3 * f + 1) * 64); G8(q2, 256 + (3 * f + 2) * 64);
#pragma unroll
            for (int j = 0; j < 8; j++)
                v[j] = fmaf(m[2], q2[j], fmaf(m[1], q1[j], m[0] * q0[j])); } break;
        case 13: { const float* m = ax + 256 + 9 * a;
#pragma unroll
            for (int j = 0; j < 8; j++) v[j] = 0.f;
#pragma unroll
            for (int t2 = 0; t2 < 9; t2++) {
                const float4* q_ = (const float4*)(bz + 256 + t2 * 64 + b0);
                float4 a0 = q_[0], a1 = q_[1];
                float mm = m[t2];
                v[0] = fmaf(mm, a0.x, v[0]); v[1] = fmaf(mm, a0.y, v[1]);
                v[2] = fmaf(mm, a0.z, v[2]); v[3] = fmaf(mm, a0.w, v[3]);
                v[4] = fmaf(mm, a1.x, v[4]); v[5] = fmaf(mm, a1.y, v[5]);
                v[6] = fmaf(mm, a1.z, v[6]); v[7] = fmaf(mm, a1.w, v[7]);
            } } break;
        default: { int u1 = (u + 1) % 3, u2 = (u + 2) % 3;   // p14
            const float* m1 = ax + 256 + 9 * a + 3 * u1;
            const float* m2 = ax + 256 + 9 * a + 3 * u2;
#pragma unroll
            for (int j = 0; j < 8; j++) v[j] = 0.f;
#pragma unroll
            for (int i = 0; i < 3; i++) {
                const float4* qa_ = (const float4*)(bz + 256 + (3 * u2 + i) * 64 + b0);
                const float4* qb_ = (const float4*)(bz + 256 + (3 * u1 + i) * 64 + b0);
                float4 a0 = qa_[0], a1 = qa_[1], c0 = qb_[0], c1 = qb_[1];
                float f1 = m1[i], f2 = m2[i];
                v[0] += f1 * a0.x - f2 * c0.x; v[1] += f1 * a0.y - f2 * c0.y;
                v[2] += f1 * a0.z - f2 * c0.z; v[3] += f1 * a0.w - f2 * c0.w;
                v[4] += f1 * a1.x - f2 * c1.x; v[5] += f1 * a1.y - f2 * c1.y;
                v[6] += f1 * a1.z - f2 * c1.z; v[7] += f1 * a1.w - f2 * c1.w;
            } } break;
        }
        uint32_t hp[4], lp[4];
#pragma unroll
        for (int jj = 0; jj < 4; jj++) {
            float v0 = v[2 * jj], v1 = v[2 * jj + 1];
            __nv_bfloat16 h0 = __float2bfloat16(v0), h1 = __float2bfloat16(v1);
            hp[jj] = pk2(h0, h1);
            lp[jj] = cvt2(v0 - __bfloat162float(h0), v1 - __bfloat162float(h1));
        }
        const uint32_t eo = phi_off + row * 144 + b0 * 2;
        *(uint4*)(smemc + eo) = make_uint4(hp[0], hp[1], hp[2], hp[3]);
        *(uint4*)(smemc + eo + 18432) = make_uint4(lp[0], lp[1], lp[2], lp[3]);
    }
}

__global__ void __launch_bounds__(256, 1)
tp_hmma_kernel(const float* __restrict__ x1, const float* __restrict__ x2,
               float* __restrict__ out) {
    extern __shared__ char smem[];
    float* smemf = (float*)smem;
    const int tid = threadIdx.x, w = tid >> 5, lane = tid & 31;
    const bool prod = (w < 4);
    const int ptid = tid & 127;
    const int cw = w - 4;                 // consumer warp index 0..3
    const int z0 = blockIdx.x * 14;
    const int nzv = min(14, 4096 - z0);
    const uint32_t sb = smem_u32(smem);

    // stage x1 (natural, stride 833) and x2 (component-major, stride 840) — all 256 threads
    for (int i = tid; i < 14 * 832; i += 256) {
        int z = i / 832, f = i - z * 832;
        int zg = z0 + z; if (zg > 4095) zg = 4095;
        smemf[z * 833 + f] = x1[(size_t)zg * 832 + f];
        float v2 = x2[(size_t)zg * 832 + f];
        int d;
        if (f < 64) d = f;
        else if (f < 256) { int g = f - 64; d = 64 + (g % 3) * 64 + g / 3; }
        else { int g = f - 256; d = 256 + (g % 9) * 64 + g / 9; }
        smemf[11664 + z * 840 + d] = v2;
    }

    // consumer accumulators: acc2 = Lout2 (all 4 consumer warps, 32 m-rows each, n=64);
    // accX = Lout1 on warps 4-6 (16 m-rows) OR Lout0 on warp 7 (16 m-rows)
    float acc2[2][8][4], accX[1][8][4];
#pragma unroll
    for (int mi = 0; mi < 2; mi++)
#pragma unroll
        for (int ni = 0; ni < 8; ni++)
#pragma unroll
            for (int di = 0; di < 4; di++) {
                acc2[mi][ni][di] = 0.f;
                if (mi == 0) accX[0][ni][di] = 0.f;
            }

    // prologue
    if (prod) {
        prefetch_w(0, 0, 0, sb, ptid);
        asm volatile("cp.async.commit_group;" ::: "memory");
        prefetch_w(0, 1, 1, sb, ptid);
        asm volatile("cp.async.commit_group;" ::: "memory");
    }
    __syncthreads();                        // x staged visible for gen
    if (prod) {
        gen_chunk(0, c_grp[0], 0, nzv, smemf, smem, P_OFF, ptid);
        asm volatile("cp.async.wait_group 1;" ::: "memory");   // W0 landed
    }
    __syncthreads();                        // publish P0 + W0

    // invariant at top of iter c: P[c&1] + W[c] visible; W[c+1] in flight
    for (int c = 0; c < 960; c++) {
        if (prod) {
            const int cn = c + 2;
            if (cn < 960) prefetch_w(cn >> 6, cn & 63, cn % 3, sb, ptid);
            asm volatile("cp.async.commit_group;" ::: "memory");
            const int cg = c + 1;
            if (cg < 960)
                gen_chunk(cg >> 6, c_grp[cg >> 6], cg & 63, nzv, smemf, smem,
                          P_OFF + (cg & 1) * P_STRIDE, ptid);
            asm volatile("cp.async.wait_group 1;" ::: "memory");   // W[c+1] landed
        } else {
            const int g = c_grp[c >> 6];
            const uint32_t pP = sb + P_OFF + (c & 1) * P_STRIDE;
            const uint32_t pWh = sb + W_OFF + (c % 3) * W_STRIDE;
            const uint32_t pWl = pWh + 9216;
            if (g == 2) {
                warp_mma<2>(acc2, cw * 32, pP, pP + 18432, pWh, pWl, lane);
            } else if (g == 1) {
                if (cw < 3) warp_mma<1>(&accX[0], cw * 16, pP, pP + 18432, pWh, pWl, lane);
            } else {
                if (cw == 3) warp_mma<1>(&accX[0], 0, pP, pP + 18432, pWh, pWl, lane);
            }
        }
        __syncthreads();   // publish P[(c+1)&1] and W[c+1]
    }

    if (!prod) {
        // ---- Lout2 epilogue ----
        const int m0 = cw * 32;
#pragma unroll
        for (int mi = 0; mi < 2; mi++)
#pragma unroll
            for (int ni = 0; ni < 8; ni++)
#pragma unroll
                for (int di = 0; di < 4; di++) {
                    int row = m0 + mi * 16 + (lane >> 2) + (di >> 1) * 8;
                    int col = ni * 8 + (lane & 3) * 2 + (di & 1);
                    if (row < 126) {
                        int z = row / 9, u = row - z * 9;
                        if (z < nzv)
                            out[(size_t)(z0 + z) * 832 + 256 + col * 9 + u] = acc2[mi][ni][di];
                    }
                }
        if (cw < 3) {
            // ---- Lout1 epilogue ----
            const int m1r = cw * 16;
#pragma unroll
            for (int ni = 0; ni < 8; ni++)
#pragma unroll
                for (int di = 0; di < 4; di++) {
                    int row = m1r + (lane >> 2) + (di >> 1) * 8;
                    int col = ni * 8 + (lane & 3) * 2 + (di & 1);
                    if (row < 42) {
                        int z = row / 3, u = row - z * 3;
                        if (z < nzv)
                            out[(size_t)(z0 + z) * 832 + 64 + col * 3 + u] = accX[0][ni][di];
                    }
                }
        } else {
            // ---- Lout0 epilogue ----
#pragma unroll
            for (int ni = 0; ni < 8; ni++)
#pragma unroll
                for (int di = 0; di < 4; di++) {
                    int row = (lane >> 2) + (di >> 1) * 8;
                    int col = ni * 8 + (lane & 3) * 2 + (di & 1);
                    if (row < nzv)
                        out[(size_t)(z0 + row) * 832 + col] = accX[0][ni][di];
                }
        }
    }
}

extern "C" void kernel_launch(void* const* d_in, const int* in_sizes, int n_in,
                              void* d_out, int out_size) {
    const float* x1 = (const float*)d_in[0];
    const float* x2 = (const float*)d_in[1];
    const float* w  = (const float*)d_in[2];
    float* out = (float*)d_out;

    prep_w<<<(WTE + 255) / 256, 256>>>(w);

    static int attr_set = 0;
    if (!attr_set) {
        cudaFuncSetAttribute(tp_hmma_kernel, cudaFuncAttributeMaxDynamicSharedMemorySize, SMEM_TOT);
        attr_set = 1;
    }
    tp_hmma_kernel<<<293, 256, SMEM_TOT>>>(x1, x2, out);
}

// round 10
// speedup vs baseline: 1.1329x; 1.1329x over previous
#include <cuda_runtime.h>
#include <cuda_bf16.h>
#include <cstdint>

#define WTE (15 * 64 * 4096)

__device__ __align__(16) __nv_bfloat16 g_Whi[WTE];
__device__ __align__(16) __nv_bfloat16 g_Wlo[WTE];

// group of each path: 0 -> Lout0, 1 -> Lout1, 2 -> Lout2
__constant__ int c_grp[15] = {0,1,2,1,2,0,1,1,2,2,1,2,2,0,1};

// W scratch: tiles [p][a][c][b] bf16 hi/lo, from w[p][c][a][b]
__global__ void prep_w(const float* __restrict__ w) {
    int d = blockIdx.x * 256 + threadIdx.x;
    if (d >= WTE) return;
    int p = d >> 18, a = (d >> 12) & 63, c = (d >> 6) & 63, b = d & 63;
    float f = w[(p << 18) | (c << 12) | (a << 6) | b];
    __nv_bfloat16 hi = __float2bfloat16(f);
    g_Whi[d] = hi;
    g_Wlo[d] = __float2bfloat16(f - __bfloat162float(hi));
}

// ---------- smem byte layout ----------
#define P_OFF    93696
#define P_STRIDE 36864
#define W_OFF    167424
#define W_STRIDE 18432
#define SMEM_TOT 222720
#define NTHR     512

__device__ __forceinline__ uint32_t smem_u32(const void* p) {
    uint32_t a;
    asm("{ .reg .u64 t; cvta.to.shared.u64 t, %1; cvt.u32.u64 %0, t; }" : "=r"(a) : "l"(p));
    return a;
}
__device__ __forceinline__ uint32_t pk2(__nv_bfloat16 a, __nv_bfloat16 b) {
    __nv_bfloat162 t(a, b);
    return *(uint32_t*)&t;
}
__device__ __forceinline__ uint32_t cvt2(float lo, float hi) {
    uint32_t r;
    asm("cvt.rn.bf16x2.f32 %0, %1, %2;" : "=r"(r) : "f"(hi), "f"(lo));
    return r;
}

#define LDSM4(r, addr) asm volatile( \
    "ldmatrix.sync.aligned.m8n8.x4.shared.b16 {%0,%1,%2,%3}, [%4];" \
    : "=r"((r)[0]), "=r"((r)[1]), "=r"((r)[2]), "=r"((r)[3]) : "r"(addr))

#define MMAB(d, a, bb0, bb1) asm volatile( \
    "mma.sync.aligned.m16n8k16.row.col.f32.bf16.bf16.f32 " \
    "{%0,%1,%2,%3}, {%4,%5,%6,%7}, {%8,%9}, {%0,%1,%2,%3};" \
    : "+f"((d)[0]), "+f"((d)[1]), "+f"((d)[2]), "+f"((d)[3]) \
    : "r"((a)[0]), "r"((a)[1]), "r"((a)[2]), "r"((a)[3]), "r"(bb0), "r"(bb1))

// one m-frag (16 rows) x NF n16-frags, 3 bf16 passes, K=64 (4 k-steps)
template<int NF>
__device__ __forceinline__ void warp_mma(float (*acc)[4], int m0, int n0,
                                         uint32_t pPhi, uint32_t pPlo,
                                         uint32_t pWh, uint32_t pWl, int lane) {
    const uint32_t aoff = (uint32_t)((lane & 15) * 144 + ((lane >> 4) << 4));
    const uint32_t boff = (uint32_t)(((lane & 7) + ((lane >> 4) & 1) * 8) * 144 + (lane & 8) * 2);
#pragma unroll
    for (int ks = 0; ks < 4; ks++) {
        const uint32_t kb = ks * 32;
        uint32_t ah[4], al[4];
        {
            uint32_t o = (uint32_t)(m0 * 144) + kb + aoff;
            LDSM4(ah, pPhi + o);
            LDSM4(al, pPlo + o);
        }
        uint32_t bh[NF][4], bl[NF][4];
#pragma unroll
        for (int nj = 0; nj < NF; nj++) {
            uint32_t o = (uint32_t)((n0 + nj * 16) * 144) + kb + boff;
            LDSM4(bh[nj], pWh + o);
            LDSM4(bl[nj], pWl + o);
        }
#pragma unroll
        for (int nj = 0; nj < NF; nj++)
#pragma unroll
            for (int s = 0; s < 2; s++) {
                float* d = acc[nj * 2 + s];
                MMAB(d, ah, bh[nj][s * 2], bh[nj][s * 2 + 1]);
                MMAB(d, al, bh[nj][s * 2], bh[nj][s * 2 + 1]);
                MMAB(d, ah, bl[nj][s * 2], bl[nj][s * 2 + 1]);
            }
    }
}

// 512 threads issue the whole W tile (hi+lo = 1024 x 16B) via cp.async
__device__ __forceinline__ void prefetch_w(int p, int a, int slot, uint32_t sb, int tid) {
    const size_t tile = ((size_t)(p * 64 + a)) << 12;
#pragma unroll
    for (int q = 0; q < 2; q++) {
        int i = tid + NTHR * q;
        int half = i >> 9, r = i & 511;
        int cR = r >> 3, seg = r & 7;
        const __nv_bfloat16* src = (half ? g_Wlo : g_Whi) + tile + cR * 64 + seg * 8;
        uint32_t dst = sb + W_OFF + slot * W_STRIDE + (half * 64 + cR) * 144 + seg * 16;
        asm volatile("cp.async.cg.shared.global [%0], [%1], 16;" :: "r"(dst), "l"(src));
    }
}

#define G8(nm, off) float nm[8]; { const float4* q_ = (const float4*)(bz + (off) + b0); \
    float4 t0_ = q_[0], t1_ = q_[1]; nm[0]=t0_.x; nm[1]=t0_.y; nm[2]=t0_.z; nm[3]=t0_.w; \
    nm[4]=t1_.x; nm[5]=t1_.y; nm[6]=t1_.z; nm[7]=t1_.w; }

__device__ __forceinline__ void gen_chunk(int p, int g, int a, int nzv,
                                          const float* smemf, char* smemc,
                                          uint32_t phi_off, int tid) {
    const int tasks = (g == 2) ? 1024 : (g == 1 ? 384 : 128);
    for (int t = tid; t < tasks; t += NTHR) {
        const int row = t >> 3;
        const int b0 = (t & 7) << 3;
        int z, u;
        if (g == 2)      { z = row / 9; u = row - z * 9; }
        else if (g == 1) { z = row / 3; u = row - z * 3; }
        else             { z = row;     u = 0; }
        if (z > nzv - 1) z = nzv - 1;
        const float* ax = smemf + z * 833;
        const float* bz = smemf + 11664 + z * 840;
        float v[8];
        switch (p) {
        case 0: { G8(s, 0); float A = ax[a];
#pragma unroll
            for (int j = 0; j < 8; j++) v[j] = A * s[j]; } break;
        case 1: { G8(s, 64 + u * 64); float A = ax[a];
#pragma unroll
            for (int j = 0; j < 8; j++) v[j] = A * s[j]; } break;
        case 2: { G8(s, 256 + u * 64); float A = ax[a];
#pragma unroll
            for (int j = 0; j < 8; j++) v[j] = A * s[j]; } break;
        case 3: { G8(s, 0); float A = ax[64 + 3 * a + u];
#pragma unroll
            for (int j = 0; j < 8; j++) v[j] = A * s[j]; } break;
        case 4: { G8(s, 64 + (u % 3) * 64); float A = ax[64 + 3 * a + u / 3];
#pragma unroll
            for (int j = 0; j < 8; j++) v[j] = A * s[j]; } break;
        case 5: { G8(q0, 64); G8(q1, 128); G8(q2, 192);
            const float* av = ax + 64 + 3 * a;
#pragma unroll
            for (int j = 0; j < 8; j++)
                v[j] = fmaf(av[2], q2[j], fmaf(av[1], q1[j], av[0] * q0[j])); } break;
        case 6: { int u1 = (u + 1) % 3, u2 = (u + 2) % 3;
            G8(qa, 64 + u2 * 64); G8(qb, 64 + u1 * 64);
            const float* av = ax + 64 + 3 * a;
#pragma unroll
            for (int j = 0; j < 8; j++) v[j] = av[u1] * qa[j] - av[u2] * qb[j]; } break;
        case 7: { G8(q0, 256 + (3 * u) * 64); G8(q1, 256 + (3 * u + 1) * 64); G8(q2, 256 + (3 * u + 2) * 64);
            const float* av = ax + 64 + 3 * a;
#pragma unroll
            for (int j = 0; j < 8; j++)
                v[j] = fmaf(av[2], q2[j], fmaf(av[1], q1[j], av[0] * q0[j])); } break;
        case 8: { int e = u / 3, gg = u % 3, g1 = (gg + 1) % 3, g2 = (gg + 2) % 3;
            G8(qa, 256 + (3 * e + g2) * 64); G8(qb, 256 + (3 * e + g1) * 64);
            const float* av = ax + 64 + 3 * a;
#pragma unroll
            for (int j = 0; j < 8; j++) v[j] = av[g1] * qa[j] - av[g2] * qb[j]; } break;
        case 9: { G8(s, 0); float A = ax[256 + 9 * a + u];
#pragma unroll
            for (int j = 0; j < 8; j++) v[j] = A * s[j]; } break;
        case 10: { G8(q0, 64); G8(q1, 128); G8(q2, 192);
            const float* m = ax + 256 + 9 * a + 3 * u;
#pragma unroll
            for (int j = 0; j < 8; j++)
                v[j] = fmaf(m[2], q2[j], fmaf(m[1], q1[j], m[0] * q0[j])); } break;
        case 11: { int d = u / 3, gg = u % 3, g1 = (gg + 1) % 3, g2 = (gg + 2) % 3;
            G8(qa, 64 + g2 * 64); G8(qb, 64 + g1 * 64);
            const float* m = ax + 256 + 9 * a + 3 * d;
#pragma unroll
            for (int j = 0; j < 8; j++) v[j] = m[g1] * qa[j] - m[g2] * qb[j]; } break;
        case 12: { int d = u / 3, f = u % 3;
            const float* m = ax + 256 + 9 * a + 3 * d;
            G8(q0, 256 + (3 * f) * 64); G8(q1, 256 + (3 * f + 1) * 64); G8(q2, 256 + (3 * f + 2) * 64);
#pragma unroll
            for (int j = 0; j < 8; j++)
                v[j] = fmaf(m[2], q2[j], fmaf(m[1], q1[j], m[0] * q0[j])); } break;
        case 13: { const float* m = ax + 256 + 9 * a;
#pragma unroll
            for (int j = 0; j < 8; j++) v[j] = 0.f;
#pragma unroll
            for (int t2 = 0; t2 < 9; t2++) {
                const float4* q_ = (const float4*)(bz + 256 + t2 * 64 + b0);
                float4 a0 = q_[0], a1 = q_[1];
                float mm = m[t2];
                v[0] = fmaf(mm, a0.x, v[0]); v[1] = fmaf(mm, a0.y, v[1]);
                v[2] = fmaf(mm, a0.z, v[2]); v[3] = fmaf(mm, a0.w, v[3]);
                v[4] = fmaf(mm, a1.x, v[4]); v[5] = fmaf(mm, a1.y, v[5]);
                v[6] = fmaf(mm, a1.z, v[6]); v[7] = fmaf(mm, a1.w, v[7]);
            } } break;
        default: { int u1 = (u + 1) % 3, u2 = (u + 2) % 3;   // p14
            const float* m1 = ax + 256 + 9 * a + 3 * u1;
            const float* m2 = ax + 256 + 9 * a + 3 * u2;
#pragma unroll
            for (int j = 0; j < 8; j++) v[j] = 0.f;
#pragma unroll
            for (int i = 0; i < 3; i++) {
                const float4* qa_ = (const float4*)(bz + 256 + (3 * u2 + i) * 64 + b0);
                const float4* qb_ = (const float4*)(bz + 256 + (3 * u1 + i) * 64 + b0);
                float4 a0 = qa_[0], a1 = qa_[1], c0 = qb_[0], c1 = qb_[1];
                float f1 = m1[i], f2 = m2[i];
                v[0] += f1 * a0.x - f2 * c0.x; v[1] += f1 * a0.y - f2 * c0.y;
                v[2] += f1 * a0.z - f2 * c0.z; v[3] += f1 * a0.w - f2 * c0.w;
                v[4] += f1 * a1.x - f2 * c1.x; v[5] += f1 * a1.y - f2 * c1.y;
                v[6] += f1 * a1.z - f2 * c1.z; v[7] += f1 * a1.w - f2 * c1.w;
            } } break;
        }
        uint32_t hp[4], lp[4];
#pragma unroll
        for (int jj = 0; jj < 4; jj++) {
            float v0 = v[2 * jj], v1 = v[2 * jj + 1];
            __nv_bfloat16 h0 = __float2bfloat16(v0), h1 = __float2bfloat16(v1);
            hp[jj] = pk2(h0, h1);
            lp[jj] = cvt2(v0 - __bfloat162float(h0), v1 - __bfloat162float(h1));
        }
        const uint32_t eo = phi_off + row * 144 + b0 * 2;
        *(uint4*)(smemc + eo) = make_uint4(hp[0], hp[1], hp[2], hp[3]);
        *(uint4*)(smemc + eo + 18432) = make_uint4(lp[0], lp[1], lp[2], lp[3]);
    }
}

__global__ void __launch_bounds__(NTHR, 1)
tp_hmma_kernel(const float* __restrict__ x1, const float* __restrict__ x2,
               float* __restrict__ out) {
    extern __shared__ char smem[];
    float* smemf = (float*)smem;
    const int tid = threadIdx.x, w = tid >> 5, lane = tid & 31;
    const int z0 = blockIdx.x * 14;
    const int nzv = min(14, 4096 - z0);
    const uint32_t sb = smem_u32(smem);

    // stage x1 (natural, stride 833) and x2 (component-major, stride 840)
    for (int i = tid; i < 14 * 832; i += NTHR) {
        int z = i / 832, f = i - z * 832;
        int zg = z0 + z; if (zg > 4095) zg = 4095;
        smemf[z * 833 + f] = x1[(size_t)zg * 832 + f];
        float v2 = x2[(size_t)zg * 832 + f];
        int d;
        if (f < 64) d = f;
        else if (f < 256) { int g = f - 64; d = 64 + (g % 3) * 64 + g / 3; }
        else { int g = f - 256; d = 256 + (g % 9) * 64 + g / 9; }
        smemf[11664 + z * 840 + d] = v2;
    }

    // 16 warps. g2: all warps, m-frag (w&7), n half (w>>3) -> acc2[4][4]
    // g1: warps 0-11, m-frag (w%3), n 16-slice (w/3)      -> accX[2][4]
    // g0: warps 12-15, m-frag 0,  n 16-slice (w-12)       -> accX[2][4]
    float acc2[4][4], accX[2][4];
#pragma unroll
    for (int ni = 0; ni < 4; ni++)
#pragma unroll
        for (int di = 0; di < 4; di++) {
            acc2[ni][di] = 0.f;
            if (ni < 2) accX[ni][di] = 0.f;
        }

    // prologue: W0, W1 in flight; gen chunk0; wait W0; publish
    prefetch_w(0, 0, 0, sb, tid);
    asm volatile("cp.async.commit_group;" ::: "memory");
    prefetch_w(0, 1, 1, sb, tid);
    asm volatile("cp.async.commit_group;" ::: "memory");
    __syncthreads();                        // staging visible for gen
    gen_chunk(0, c_grp[0], 0, nzv, smemf, smem, P_OFF, tid);
    asm volatile("cp.async.wait_group 1;" ::: "memory");   // W0 done
    __syncthreads();                        // publish P0 + W0

    // invariant at top of iter c: P[c&1] + W[c] visible to all; W[c+1] in flight
    for (int c = 0; c < 960; c++) {
        const int cn = c + 2;
        if (cn < 960) prefetch_w(cn >> 6, cn & 63, cn % 3, sb, tid);
        asm volatile("cp.async.commit_group;" ::: "memory");
        const int cg = c + 1;
        if (cg < 960)
            gen_chunk(cg >> 6, c_grp[cg >> 6], cg & 63, nzv, smemf, smem,
                      P_OFF + (cg & 1) * P_STRIDE, tid);
        asm volatile("cp.async.wait_group 1;" ::: "memory");   // W[c+1] landed
        const int g = c_grp[c >> 6];
        const uint32_t pP = sb + P_OFF + (c & 1) * P_STRIDE;
        const uint32_t pWh = sb + W_OFF + (c % 3) * W_STRIDE;
        const uint32_t pWl = pWh + 9216;
        if (g == 2) {
            warp_mma<2>(acc2, (w & 7) * 16, (w >> 3) * 32, pP, pP + 18432, pWh, pWl, lane);
        } else if (g == 1) {
            if (w < 12) warp_mma<1>(accX, (w % 3) * 16, (w / 3) * 16, pP, pP + 18432, pWh, pWl, lane);
        } else {
            if (w >= 12) warp_mma<1>(accX, 0, (w - 12) * 16, pP, pP + 18432, pWh, pWl, lane);
        }
        __syncthreads();   // publish P[(c+1)&1] and W[c+1]
    }

    // ---- epilogue (D frag: row=(l>>2)+8*(di>>1), col=2*(l&3)+(di&1)) ----
    {
        const int m0 = (w & 7) * 16, n0 = (w >> 3) * 32;
#pragma unroll
        for (int ni = 0; ni < 4; ni++)
#pragma unroll
            for (int di = 0; di < 4; di++) {
                int row = m0 + (lane >> 2) + (di >> 1) * 8;
                int col = n0 + ni * 8 + (lane & 3) * 2 + (di & 1);
                if (row < 126) {
                    int z = row / 9, u = row - z * 9;
                    if (z < nzv)
                        out[(size_t)(z0 + z) * 832 + 256 + col * 9 + u] = acc2[ni][di];
                }
            }
    }
    if (w < 12) {
        const int m0 = (w % 3) * 16, n0 = (w / 3) * 16;
#pragma unroll
        for (int ni = 0; ni < 2; ni++)
#pragma unroll
            for (int di = 0; di < 4; di++) {
                int row = m0 + (lane >> 2) + (di >> 1) * 8;
                int col = n0 + ni * 8 + (lane & 3) * 2 + (di & 1);
                if (row < 42) {
                    int z = row / 3, u = row - z * 3;
                    if (z < nzv)
                        out[(size_t)(z0 + z) * 832 + 64 + col * 3 + u] = accX[ni][di];
                }
            }
    } else {
        const int n0 = (w - 12) * 16;
#pragma unroll
        for (int ni = 0; ni < 2; ni++)
#pragma unroll
            for (int di = 0; di < 4; di++) {
                int row = (lane >> 2) + (di >> 1) * 8;
                int col = n0 + ni * 8 + (lane & 3) * 2 + (di & 1);
                if (row < nzv)
                    out[(size_t)(z0 + row) * 832 + col] = accX[ni][di];
            }
    }
}

extern "C" void kernel_launch(void* const* d_in, const int* in_sizes, int n_in,
                              void* d_out, int out_size) {
    const float* x1 = (const float*)d_in[0];
    const float* x2 = (const float*)d_in[1];
    const float* w  = (const float*)d_in[2];
    float* out = (float*)d_out;

    prep_w<<<(WTE + 255) / 256, 256>>>(w);

    static int attr_set = 0;
    if (!attr_set) {
        cudaFuncSetAttribute(tp_hmma_kernel, cudaFuncAttributeMaxDynamicSharedMemorySize, SMEM_TOT);
        attr_set = 1;
    }
    tp_hmma_kernel<<<293, NTHR, SMEM_TOT>>>(x1, x2, out);
}

// round 11
// speedup vs baseline: 1.5755x; 1.3907x over previous
#include <cuda_runtime.h>
#include <cuda_fp16.h>
#include <cstdint>

#define WTE (15 * 64 * 4096)

// fp16 W tiles [p][a][c][b], pre-scaled by 1024 (epilogue multiplies by 2^-10)
__device__ __align__(16) __half g_Wf[WTE];

// group of each path: 0 -> Lout0, 1 -> Lout1, 2 -> Lout2
__constant__ int c_grp[15] = {0,1,2,1,2,0,1,1,2,2,1,2,2,0,1};

__global__ void prep_w(const float* __restrict__ w) {
    int d = blockIdx.x * 256 + threadIdx.x;
    if (d >= WTE) return;
    int p = d >> 18, a = (d >> 12) & 63, c = (d >> 6) & 63, b = d & 63;
    float f = w[(p << 18) | (c << 12) | (a << 6) | b];
    g_Wf[d] = __float2half(f * 1024.0f);
}

// ---------- smem byte layout ----------
// x1: 14*833*4 = 46648 -> region [0, 46656)
// x2T: [46656, 93696)  (14*840*4 = 47040)
// P: 2 stages * 18432 = 36864 -> [93696, 130560)
// W: 3 slots * 9216 = 27648   -> [130560, 158208)
#define P_OFF    93696
#define P_STRIDE 18432
#define W_OFF    130560
#define W_STRIDE 9216
#define SMEM_TOT 158208
#define NTHR     512

__device__ __forceinline__ uint32_t smem_u32(const void* p) {
    uint32_t a;
    asm("{ .reg .u64 t; cvta.to.shared.u64 t, %1; cvt.u32.u64 %0, t; }" : "=r"(a) : "l"(p));
    return a;
}

#define LDSM4(r, addr) asm volatile( \
    "ldmatrix.sync.aligned.m8n8.x4.shared.b16 {%0,%1,%2,%3}, [%4];" \
    : "=r"((r)[0]), "=r"((r)[1]), "=r"((r)[2]), "=r"((r)[3]) : "r"(addr))

#define MMAF(d, a, bb0, bb1) asm volatile( \
    "mma.sync.aligned.m16n8k16.row.col.f32.f16.f16.f32 " \
    "{%0,%1,%2,%3}, {%4,%5,%6,%7}, {%8,%9}, {%0,%1,%2,%3};" \
    : "+f"((d)[0]), "+f"((d)[1]), "+f"((d)[2]), "+f"((d)[3]) \
    : "r"((a)[0]), "r"((a)[1]), "r"((a)[2]), "r"((a)[3]), "r"(bb0), "r"(bb1))

// one m-frag (16 rows) x NF n16-frags, single fp16 pass, K=64 (4 k-steps)
template<int NF>
__device__ __forceinline__ void warp_mma(float (*acc)[4], int m0, int n0,
                                         uint32_t pP, uint32_t pW, int lane) {
    const uint32_t aoff = (uint32_t)((lane & 15) * 144 + ((lane >> 4) << 4));
    const uint32_t boff = (uint32_t)(((lane & 7) + ((lane >> 4) & 1) * 8) * 144 + (lane & 8) * 2);
#pragma unroll
    for (int ks = 0; ks < 4; ks++) {
        const uint32_t kb = ks * 32;
        uint32_t ah[4];
        LDSM4(ah, pP + (uint32_t)(m0 * 144) + kb + aoff);
        uint32_t bh[NF][4];
#pragma unroll
        for (int nj = 0; nj < NF; nj++)
            LDSM4(bh[nj], pW + (uint32_t)((n0 + nj * 16) * 144) + kb + boff);
#pragma unroll
        for (int nj = 0; nj < NF; nj++)
#pragma unroll
            for (int s = 0; s < 2; s++)
                MMAF(acc[nj * 2 + s], ah, bh[nj][s * 2], bh[nj][s * 2 + 1]);
    }
}

// 512 threads issue the whole 9KB W tile (512 x 16B) via cp.async
__device__ __forceinline__ void prefetch_w(int p, int a, int slot, uint32_t sb, int tid) {
    const size_t tile = ((size_t)(p * 64 + a)) << 12;
    int cR = tid >> 3, seg = tid & 7;
    const __half* src = g_Wf + tile + cR * 64 + seg * 8;
    uint32_t dst = sb + W_OFF + slot * W_STRIDE + cR * 144 + seg * 16;
    asm volatile("cp.async.cg.shared.global [%0], [%1], 16;" :: "r"(dst), "l"(src));
}

#define G8(nm, off) float nm[8]; { const float4* q_ = (const float4*)(bz + (off) + b0); \
    float4 t0_ = q_[0], t1_ = q_[1]; nm[0]=t0_.x; nm[1]=t0_.y; nm[2]=t0_.z; nm[3]=t0_.w; \
    nm[4]=t1_.x; nm[5]=t1_.y; nm[6]=t1_.z; nm[7]=t1_.w; }

__device__ __forceinline__ void gen_chunk(int p, int g, int a, int nzv,
                                          const float* smemf, char* smemc,
                                          uint32_t pdst, int tid) {
    const int tasks = (g == 2) ? 1024 : (g == 1 ? 384 : 128);
    for (int t = tid; t < tasks; t += NTHR) {
        const int row = t >> 3;
        const int b0 = (t & 7) << 3;
        int z, u;
        if (g == 2)      { z = row / 9; u = row - z * 9; }
        else if (g == 1) { z = row / 3; u = row - z * 3; }
        else             { z = row;     u = 0; }
        if (z > nzv - 1) z = nzv - 1;
        const float* ax = smemf + z * 833;
        const float* bz = smemf + 11664 + z * 840;
        float v[8];
        switch (p) {
        case 0: { G8(s, 0); float A = ax[a];
#pragma unroll
            for (int j = 0; j < 8; j++) v[j] = A * s[j]; } break;
        case 1: { G8(s, 64 + u * 64); float A = ax[a];
#pragma unroll
            for (int j = 0; j < 8; j++) v[j] = A * s[j]; } break;
        case 2: { G8(s, 256 + u * 64); float A = ax[a];
#pragma unroll
            for (int j = 0; j < 8; j++) v[j] = A * s[j]; } break;
        case 3: { G8(s, 0); float A = ax[64 + 3 * a + u];
#pragma unroll
            for (int j = 0; j < 8; j++) v[j] = A * s[j]; } break;
        case 4: { G8(s, 64 + (u % 3) * 64); float A = ax[64 + 3 * a + u / 3];
#pragma unroll
            for (int j = 0; j < 8; j++) v[j] = A * s[j]; } break;
        case 5: { G8(q0, 64); G8(q1, 128); G8(q2, 192);
            const float* av = ax + 64 + 3 * a;
#pragma unroll
            for (int j = 0; j < 8; j++)
                v[j] = fmaf(av[2], q2[j], fmaf(av[1], q1[j], av[0] * q0[j])); } break;
        case 6: { int u1 = (u + 1) % 3, u2 = (u + 2) % 3;
            G8(qa, 64 + u2 * 64); G8(qb, 64 + u1 * 64);
            const float* av = ax + 64 + 3 * a;
#pragma unroll
            for (int j = 0; j < 8; j++) v[j] = av[u1] * qa[j] - av[u2] * qb[j]; } break;
        case 7: { G8(q0, 256 + (3 * u) * 64); G8(q1, 256 + (3 * u + 1) * 64); G8(q2, 256 + (3 * u + 2) * 64);
            const float* av = ax + 64 + 3 * a;
#pragma unroll
            for (int j = 0; j < 8; j++)
                v[j] = fmaf(av[2], q2[j], fmaf(av[1], q1[j], av[0] * q0[j])); } break;
        case 8: { int e = u / 3, gg = u % 3, g1 = (gg + 1) % 3, g2 = (gg + 2) % 3;
            G8(qa, 256 + (3 * e + g2) * 64); G8(qb, 256 + (3 * e + g1) * 64);
            const float* av = ax + 64 + 3 * a;
#pragma unroll
            for (int j = 0; j < 8; j++) v[j] = av[g1] * qa[j] - av[g2] * qb[j]; } break;
        case 9: { G8(s, 0); float A = ax[256 + 9 * a + u];
#pragma unroll
            for (int j = 0; j < 8; j++) v[j] = A * s[j]; } break;
        case 10: { G8(q0, 64); G8(q1, 128); G8(q2, 192);
            const float* m = ax + 256 + 9 * a + 3 * u;
#pragma unroll
            for (int j = 0; j < 8; j++)
                v[j] = fmaf(m[2], q2[j], fmaf(m[1], q1[j], m[0] * q0[j])); } break;
        case 11: { int d = u / 3, gg = u % 3, g1 = (gg + 1) % 3, g2 = (gg + 2) % 3;
            G8(qa, 64 + g2 * 64); G8(qb, 64 + g1 * 64);
            const float* m = ax + 256 + 9 * a + 3 * d;
#pragma unroll
            for (int j = 0; j < 8; j++) v[j] = m[g1] * qa[j] - m[g2] * qb[j]; } break;
        case 12: { int d = u / 3, f = u % 3;
            const float* m = ax + 256 + 9 * a + 3 * d;
            G8(q0, 256 + (3 * f) * 64); G8(q1, 256 + (3 * f + 1) * 64); G8(q2, 256 + (3 * f + 2) * 64);
#pragma unroll
            for (int j = 0; j < 8; j++)
                v[j] = fmaf(m[2], q2[j], fmaf(m[1], q1[j], m[0] * q0[j])); } break;
        case 13: { const float* m = ax + 256 + 9 * a;
#pragma unroll
            for (int j = 0; j < 8; j++) v[j] = 0.f;
#pragma unroll
            for (int t2 = 0; t2 < 9; t2++) {
                const float4* q_ = (const float4*)(bz + 256 + t2 * 64 + b0);
                float4 a0 = q_[0], a1 = q_[1];
                float mm = m[t2];
                v[0] = fmaf(mm, a0.x, v[0]); v[1] = fmaf(mm, a0.y, v[1]);
                v[2] = fmaf(mm, a0.z, v[2]); v[3] = fmaf(mm, a0.w, v[3]);
                v[4] = fmaf(mm, a1.x, v[4]); v[5] = fmaf(mm, a1.y, v[5]);
                v[6] = fmaf(mm, a1.z, v[6]); v[7] = fmaf(mm, a1.w, v[7]);
            } } break;
        default: { int u1 = (u + 1) % 3, u2 = (u + 2) % 3;   // p14
            const float* m1 = ax + 256 + 9 * a + 3 * u1;
            const float* m2 = ax + 256 + 9 * a + 3 * u2;
#pragma unroll
            for (int j = 0; j < 8; j++) v[j] = 0.f;
#pragma unroll
            for (int i = 0; i < 3; i++) {
                const float4* qa_ = (const float4*)(bz + 256 + (3 * u2 + i) * 64 + b0);
                const float4* qb_ = (const float4*)(bz + 256 + (3 * u1 + i) * 64 + b0);
                float4 a0 = qa_[0], a1 = qa_[1], c0 = qb_[0], c1 = qb_[1];
                float f1 = m1[i], f2 = m2[i];
                v[0] += f1 * a0.x - f2 * c0.x; v[1] += f1 * a0.y - f2 * c0.y;
                v[2] += f1 * a0.z - f2 * c0.z; v[3] += f1 * a0.w - f2 * c0.w;
                v[4] += f1 * a1.x - f2 * c1.x; v[5] += f1 * a1.y - f2 * c1.y;
                v[6] += f1 * a1.z - f2 * c1.z; v[7] += f1 * a1.w - f2 * c1.w;
            } } break;
        }
        uint32_t hp[4];
#pragma unroll
        for (int jj = 0; jj < 4; jj++) {
            __half2 h = __floats2half2_rn(v[2 * jj], v[2 * jj + 1]);
            hp[jj] = *(uint32_t*)&h;
        }
        *(uint4*)(smemc + pdst + row * 144 + b0 * 2) = make_uint4(hp[0], hp[1], hp[2], hp[3]);
    }
}

__global__ void __launch_bounds__(NTHR, 1)
tp_hmma_kernel(const float* __restrict__ x1, const float* __restrict__ x2,
               float* __restrict__ out) {
    extern __shared__ char smem[];
    float* smemf = (float*)smem;
    const int tid = threadIdx.x, w = tid >> 5, lane = tid & 31;
    const int z0 = blockIdx.x * 14;
    const int nzv = min(14, 4096 - z0);
    const uint32_t sb = smem_u32(smem);
    const float SCL = 1.0f / 1024.0f;   // undo the W*1024 prescale

    // stage x1 (natural, stride 833) and x2 (component-major, stride 840)
    for (int i = tid; i < 14 * 832; i += NTHR) {
        int z = i / 832, f = i - z * 832;
        int zg = z0 + z; if (zg > 4095) zg = 4095;
        smemf[z * 833 + f] = x1[(size_t)zg * 832 + f];
        float v2 = x2[(size_t)zg * 832 + f];
        int d;
        if (f < 64) d = f;
        else if (f < 256) { int g = f - 64; d = 64 + (g % 3) * 64 + g / 3; }
        else { int g = f - 256; d = 256 + (g % 9) * 64 + g / 9; }
        smemf[11664 + z * 840 + d] = v2;
    }

    // 16 warps. g2: all warps, m-frag (w&7), n half (w>>3) -> acc2[4][4]
    // g1: warps 0-11, m-frag (w%3), n 16-slice (w/3)      -> accX[2][4]
    // g0: warps 12-15, m-frag 0,  n 16-slice (w-12)       -> accX[2][4]
    float acc2[4][4], accX[2][4];
#pragma unroll
    for (int ni = 0; ni < 4; ni++)
#pragma unroll
        for (int di = 0; di < 4; di++) {
            acc2[ni][di] = 0.f;
            if (ni < 2) accX[ni][di] = 0.f;
        }

    // prologue: W0, W1 in flight; gen chunk0; wait W0; publish
    prefetch_w(0, 0, 0, sb, tid);
    asm volatile("cp.async.commit_group;" ::: "memory");
    prefetch_w(0, 1, 1, sb, tid);
    asm volatile("cp.async.commit_group;" ::: "memory");
    __syncthreads();                        // staging visible for gen
    gen_chunk(0, c_grp[0], 0, nzv, smemf, smem, P_OFF, tid);
    asm volatile("cp.async.wait_group 1;" ::: "memory");   // W0 done
    __syncthreads();                        // publish P0 + W0

    // invariant at top of iter c: P[c&1] + W[c] visible to all; W[c+1] in flight
    for (int c = 0; c < 960; c++) {
        const int cn = c + 2;
        if (cn < 960) prefetch_w(cn >> 6, cn & 63, cn % 3, sb, tid);
        asm volatile("cp.async.commit_group;" ::: "memory");
        const int cg = c + 1;
        if (cg < 960)
            gen_chunk(cg >> 6, c_grp[cg >> 6], cg & 63, nzv, smemf, smem,
                      P_OFF + (cg & 1) * P_STRIDE, tid);
        asm volatile("cp.async.wait_group 1;" ::: "memory");   // W[c+1] landed
        const int g = c_grp[c >> 6];
        const uint32_t pP = sb + P_OFF + (c & 1) * P_STRIDE;
        const uint32_t pW = sb + W_OFF + (c % 3) * W_STRIDE;
        if (g == 2) {
            warp_mma<2>(acc2, (w & 7) * 16, (w >> 3) * 32, pP, pW, lane);
        } else if (g == 1) {
            if (w < 12) warp_mma<1>(accX, (w % 3) * 16, (w / 3) * 16, pP, pW, lane);
        } else {
            if (w >= 12) warp_mma<1>(accX, 0, (w - 12) * 16, pP, pW, lane);
        }
        __syncthreads();   // publish P[(c+1)&1] and W[c+1]
    }

    // ---- epilogue (D frag: row=(l>>2)+8*(di>>1), col=2*(l&3)+(di&1)); scale by 2^-10 ----
    {
        const int m0 = (w & 7) * 16, n0 = (w >> 3) * 32;
#pragma unroll
        for (int ni = 0; ni < 4; ni++)
#pragma unroll
            for (int di = 0; di < 4; di++) {
                int row = m0 + (lane >> 2) + (di >> 1) * 8;
                int col = n0 + ni * 8 + (lane & 3) * 2 + (di & 1);
                if (row < 126) {
                    int z = row / 9, u = row - z * 9;
                    if (z < nzv)
                        out[(size_t)(z0 + z) * 832 + 256 + col * 9 + u] = acc2[ni][di] * SCL;
                }
            }
    }
    if (w < 12) {
        const int m0 = (w % 3) * 16, n0 = (w / 3) * 16;
#pragma unroll
        for (int ni = 0; ni < 2; ni++)
#pragma unroll
            for (int di = 0; di < 4; di++) {
                int row = m0 + (lane >> 2) + (di >> 1) * 8;
                int col = n0 + ni * 8 + (lane & 3) * 2 + (di & 1);
                if (row < 42) {
                    int z = row / 3, u = row - z * 3;
                    if (z < nzv)
                        out[(size_t)(z0 + z) * 832 + 64 + col * 3 + u] = accX[ni][di] * SCL;
                }
            }
    } else {
        const int n0 = (w - 12) * 16;
#pragma unroll
        for (int ni = 0; ni < 2; ni++)
#pragma unroll
            for (int di = 0; di < 4; di++) {
                int row = (lane >> 2) + (di >> 1) * 8;
                int col = n0 + ni * 8 + (lane & 3) * 2 + (di & 1);
                if (row < nzv)
                    out[(size_t)(z0 + row) * 832 + col] = accX[ni][di] * SCL;
            }
    }
}

extern "C" void kernel_launch(void* const* d_in, const int* in_sizes, int n_in,
                              void* d_out, int out_size) {
    const float* x1 = (const float*)d_in[0];
    const float* x2 = (const float*)d_in[1];
    const float* w  = (const float*)d_in[2];
    float* out = (float*)d_out;

    prep_w<<<(WTE + 255) / 256, 256>>>(w);

    static int attr_set = 0;
    if (!attr_set) {
        cudaFuncSetAttribute(tp_hmma_kernel, cudaFuncAttributeMaxDynamicSharedMemorySize, SMEM_TOT);
        attr_set = 1;
    }
    tp_hmma_kernel<<<293, NTHR, SMEM_TOT>>>(x1, x2, out);
}